// round 7
// baseline (speedup 1.0000x reference)
#include <cuda_runtime.h>
#include <cuda_fp16.h>
#include <cstdint>

#define NTOK   256
#define NPAIRS 512
#define NEXP   8

// ---------------- scratch (device globals) ----------------------------------
__device__ int    g_cnt[NEXP];
__device__ int    g_pairs[NEXP][NPAIRS];
__device__ int    g_pos[NPAIRS];
__device__ __align__(16) __half g_Ah  [NEXP * 512 * 2048];   // gathered x rows, fp16
__device__ __align__(16) __half g_actE[NEXP * 512 * 1024];   // silu(gate)*up, fp16
__device__ float  g_yE  [NEXP * 512 * 2048];                 // GEMM2 out

// ---------------- helpers ----------------------------------------------------
__device__ __forceinline__ uint32_t smem_u32(const void* p) {
    uint32_t a;
    asm("{ .reg .u64 t; cvta.to.shared.u64 t, %1; cvt.u32.u64 %0, t; }" : "=r"(a) : "l"(p));
    return a;
}
__device__ __forceinline__ uint32_t pack_h2(float lo, float hi) {
    uint32_t r;
    asm("cvt.rn.f16x2.f32 %0, %1, %2;" : "=r"(r) : "f"(hi), "f"(lo));
    return r;
}
__device__ __forceinline__ void cpa16(uint32_t dst, const void* src) {
    asm volatile("cp.async.cg.shared.global [%0], [%1], 16;" :: "r"(dst), "l"(src));
}
#define CP_COMMIT() asm volatile("cp.async.commit_group;" ::: "memory")
#define CP_WAIT2()  asm volatile("cp.async.wait_group 2;" ::: "memory")

__device__ __forceinline__ void sts128(uint32_t a, uint32_t x, uint32_t y, uint32_t z, uint32_t w) {
    asm volatile("st.shared.v4.b32 [%0], {%1, %2, %3, %4};" :: "r"(a), "r"(x), "r"(y), "r"(z), "r"(w) : "memory");
}
__device__ __forceinline__ void ldsm4(uint32_t& r0, uint32_t& r1, uint32_t& r2, uint32_t& r3, uint32_t a) {
    asm volatile("ldmatrix.sync.aligned.m8n8.x4.shared.b16 {%0,%1,%2,%3}, [%4];"
                 : "=r"(r0), "=r"(r1), "=r"(r2), "=r"(r3) : "r"(a));
}
__device__ __forceinline__ void ldsm2(uint32_t& r0, uint32_t& r1, uint32_t a) {
    asm volatile("ldmatrix.sync.aligned.m8n8.x2.shared.b16 {%0,%1}, [%2];"
                 : "=r"(r0), "=r"(r1) : "r"(a));
}
__device__ __forceinline__ void mma16(float* c, const uint32_t* a, const uint32_t* b) {
    asm volatile("mma.sync.aligned.m16n8k16.row.col.f32.f16.f16.f32 "
                 "{%0,%1,%2,%3}, {%4,%5,%6,%7}, {%8,%9}, {%0,%1,%2,%3};"
                 : "+f"(c[0]), "+f"(c[1]), "+f"(c[2]), "+f"(c[3])
                 : "r"(a[0]), "r"(a[1]), "r"(a[2]), "r"(a[3]), "r"(b[0]), "r"(b[1]));
}

// ---------------- routing ----------------------------------------------------
__global__ void route_kernel(const int* __restrict__ ids) {
    int tid = threadIdx.x;
    if (tid < NEXP) g_cnt[tid] = 0;
    __syncthreads();
    int e   = ids[tid] & 7;
    int pos = atomicAdd(&g_cnt[e], 1);
    g_pairs[e][pos] = tid;
    g_pos[tid] = e * 512 + pos;
}

// ---------------- gather x rows into padded fp16 A ----------------------------
__global__ void gather_kernel(const float* __restrict__ x) {
    int bid = blockIdx.x;               // (e, m)
    int e = bid >> 9, m = bid & 511;
    int cnt = g_cnt[e];
    int lim = (cnt + 63) & ~63;
    if (m >= lim) return;
    uint4* dst = (uint4*)(g_Ah + ((size_t)e * 512 + m) * 2048);
    int tid = threadIdx.x;
    if (m < cnt) {
        int p = g_pairs[e][m];
        const float4* src = (const float4*)(x + (size_t)(p >> 1) * 2048) + tid * 2;
        float4 v0 = src[0], v1 = src[1];
        uint4 o;
        o.x = pack_h2(v0.x, v0.y); o.y = pack_h2(v0.z, v0.w);
        o.z = pack_h2(v1.x, v1.y); o.w = pack_h2(v1.z, v1.w);
        dst[tid] = o;
    } else {
        dst[tid] = make_uint4(0, 0, 0, 0);
    }
}

// ---------------- fp16 mma.sync GEMM, cp.async weight ring ---------------------
// BM=64, BN=128, BK=32; 256 threads; warps 2(m) x 4(n), warp tile 32x32.
// Ring: 4 stages of { B raw fp32 (128 rows x 144B pad), A fp16 (64 rows x 80B pad) }.
// Convert (dequant fp32 -> fp16, scale folded) runs one stage ahead into a
// 2-deep fp16 B buffer (128 rows x 80B). One __syncthreads per iter.
// SMEM: 4*18432 + 4*5120 + 2*10240 = 114688 B -> 2 CTAs/SM.
#define BF32_OFF 0u
#define A_OFF    73728u
#define BH_OFF   94208u
#define SMEM_DYN 114688

template<int KTOT, bool G1>
__global__ void __launch_bounds__(256, 2) mma_gemm(
    const float* __restrict__ Ball,
    const float* __restrict__ Sall)
{
    constexpr int KS = KTOT / 32;
    constexpr int KB = KTOT / 128;

    const int e   = blockIdx.z;
    const int cnt = g_cnt[e];
    const int m0  = blockIdx.y << 6;
    if (m0 >= cnt) return;
    const int n0  = G1 ? (blockIdx.x << 6) : (blockIdx.x << 7);

    const __half* Ah = (G1 ? g_Ah : g_actE) + ((size_t)e * 512 + m0) * KTOT;

    extern __shared__ float dsm[];
    const uint32_t sb = smem_u32(dsm);

    const int tid  = threadIdx.x;
    const int lane = tid & 31, w = tid >> 5;
    const int warpM = (w & 1) << 5;     // 0 or 32
    const int warpN = (w >> 1) << 5;    // 0,32,64,96

    // cp.async geometry: A — thread t owns row t>>2, 16B granule t&3
    const int arow = tid >> 2, ac16 = tid & 3;
    const uint32_t adst0 = sb + A_OFF + (uint32_t)(arow * 80 + ac16 * 16);
    const __half* asrc0  = Ah + (size_t)arow * KTOT + ac16 * 8;

    // B — thread t owns row t>>1 (0..127), 64B half t&1 (4 granules)
    const int brow = tid >> 1, bhalf = tid & 1;
    const int bn = G1 ? ((brow < 64) ? (n0 + brow) : (1024 + n0 + brow - 64))
                      : (n0 + brow);
    const float* bsrc0 = Ball + ((size_t)e * 2048 + bn) * KTOT + bhalf * 16;
    const uint32_t bdst0 = sb + BF32_OFF + (uint32_t)(brow * 144 + bhalf * 64);

    // dequant scale row for this thread's B row
    const float* Sme = G1
        ? (Sall + ((size_t)e * 16 + ((brow < 64) ? 0 : 8) + (n0 >> 7)) * KB)
        : (Sall + ((size_t)e * 16 + (n0 >> 7)) * KB);

    // ldmatrix fragment bases (80B row stride -> conflict-free)
    const int l2 = lane & 15;
    const uint32_t aFB = (uint32_t)((warpM + l2) * 80 + (lane >> 4) * 16);
    const uint32_t bFB = (uint32_t)((warpN + (l2 & 7)) * 80 + ((l2 >> 3) & 1) * 16);

    float acc[2][4][4] = {};

    auto issue = [&](int st) {
        cpa16(adst0 + (uint32_t)((st & 3) * 5120), asrc0 + st * 32);
        const float* bs = bsrc0 + st * 32;
        uint32_t bd = bdst0 + (uint32_t)((st & 3) * 18432);
        cpa16(bd,      bs);     cpa16(bd + 16, bs + 4);
        cpa16(bd + 32, bs + 8); cpa16(bd + 48, bs + 12);
    };
    auto convert = [&](int st) {
        const float* p = dsm + ((st & 3) * 18432 + brow * 144 + bhalf * 64) / 4;
        const float sc = Sme[st >> 2];
        float4 u  = *(const float4*)(p);
        float4 v  = *(const float4*)(p + 4);
        float4 u2 = *(const float4*)(p + 8);
        float4 v2 = *(const float4*)(p + 12);
        uint32_t bd = sb + BH_OFF + (uint32_t)((st & 1) * 10240 + brow * 80 + bhalf * 32);
        sts128(bd,      pack_h2(u.x * sc,  u.y * sc),  pack_h2(u.z * sc,  u.w * sc),
                        pack_h2(v.x * sc,  v.y * sc),  pack_h2(v.z * sc,  v.w * sc));
        sts128(bd + 16, pack_h2(u2.x * sc, u2.y * sc), pack_h2(u2.z * sc, u2.w * sc),
                        pack_h2(v2.x * sc, v2.y * sc), pack_h2(v2.z * sc, v2.w * sc));
    };

    // -------- prologue: stages 0..2 in flight; convert stage 0 --------
    issue(0); CP_COMMIT();
    issue(1); CP_COMMIT();
    issue(2); CP_COMMIT();
    CP_WAIT2();                         // stage 0 landed
    convert(0);
    __syncthreads();

    // -------- main loop --------
    for (int s = 0; s < KS; s++) {
        if (s + 3 < KS) issue(s + 3);
        CP_COMMIT();

        // compute stage s (A from ring, B from fp16 buffer converted last iter)
        const uint32_t aS = sb + A_OFF  + (uint32_t)((s & 3) * 5120);
        const uint32_t bS = sb + BH_OFF + (uint32_t)((s & 1) * 10240);
#pragma unroll
        for (int ss = 0; ss < 2; ss++) {
            uint32_t af[2][4], bf[4][2];
#pragma unroll
            for (int mt = 0; mt < 2; mt++)
                ldsm4(af[mt][0], af[mt][1], af[mt][2], af[mt][3],
                      aS + aFB + (uint32_t)(mt * 1280 + ss * 32));
#pragma unroll
            for (int nt = 0; nt < 4; nt++)
                ldsm2(bf[nt][0], bf[nt][1], bS + bFB + (uint32_t)(nt * 640 + ss * 32));
#pragma unroll
            for (int mt = 0; mt < 2; mt++)
#pragma unroll
                for (int nt = 0; nt < 4; nt++)
                    mma16(acc[mt][nt], af[mt], bf[nt]);
        }

        CP_WAIT2();                     // stage s+1 landed
        if (s + 1 < KS) convert(s + 1);
        __syncthreads();
    }

    // -------- epilogue --------
    const int rr = lane >> 2, cc = (lane & 3) << 1;
    if (!G1) {
        float* Cb = g_yE + ((size_t)e * 512 + m0) * 2048 + n0;
#pragma unroll
        for (int mt = 0; mt < 2; mt++)
#pragma unroll
            for (int nt = 0; nt < 4; nt++) {
                float* p0 = Cb + (size_t)(warpM + mt * 16 + rr) * 2048 + warpN + nt * 8 + cc;
                *(float2*)p0 = make_float2(acc[mt][nt][0], acc[mt][nt][1]);
                *(float2*)(p0 + 8 * 2048) = make_float2(acc[mt][nt][2], acc[mt][nt][3]);
            }
    } else {
        // fused silu(gate)*up; up warps (w>=4) stage accs through smem
        float* ups = dsm;               // 64 x 68 floats, reuses ring space
        if (w >= 4) {
            const int wn = warpN - 64;
#pragma unroll
            for (int mt = 0; mt < 2; mt++)
#pragma unroll
                for (int nt = 0; nt < 4; nt++) {
                    int row = warpM + mt * 16 + rr;
                    int col = wn + nt * 8 + cc;
                    *(float2*)(ups + row * 68 + col)       = make_float2(acc[mt][nt][0], acc[mt][nt][1]);
                    *(float2*)(ups + (row + 8) * 68 + col) = make_float2(acc[mt][nt][2], acc[mt][nt][3]);
                }
        }
        __syncthreads();
        if (w < 4) {
            __half* act = g_actE + ((size_t)e * 512 + m0) * 1024 + n0;
#pragma unroll
            for (int mt = 0; mt < 2; mt++)
#pragma unroll
                for (int nt = 0; nt < 4; nt++) {
                    int row = warpM + mt * 16 + rr;
                    int col = warpN + nt * 8 + cc;
                    float2 u0 = *(float2*)(ups + row * 68 + col);
                    float2 u1 = *(float2*)(ups + (row + 8) * 68 + col);
                    float g0 = acc[mt][nt][0], g1 = acc[mt][nt][1];
                    float g2 = acc[mt][nt][2], g3 = acc[mt][nt][3];
                    float a0 = g0 / (1.f + __expf(-g0)) * u0.x;
                    float a1 = g1 / (1.f + __expf(-g1)) * u0.y;
                    float a2 = g2 / (1.f + __expf(-g2)) * u1.x;
                    float a3 = g3 / (1.f + __expf(-g3)) * u1.y;
                    *(uint32_t*)(act + (size_t)row * 1024 + col)       = pack_h2(a0, a1);
                    *(uint32_t*)(act + (size_t)(row + 8) * 1024 + col) = pack_h2(a2, a3);
                }
        }
    }
}

// ---------------- combine -------------------------------------------------------
__global__ void combine_kernel(const float* __restrict__ tw,
                               float* __restrict__ out) {
    int idx = blockIdx.x * 256 + threadIdx.x;     // over 256*2048/4
    int t  = idx >> 9;
    int h4 = (idx & 511) << 2;
    float w0 = tw[2 * t + 0], w1 = tw[2 * t + 1];
    const float4* y0 = (const float4*)(g_yE + (size_t)g_pos[2 * t + 0] * 2048 + h4);
    const float4* y1 = (const float4*)(g_yE + (size_t)g_pos[2 * t + 1] * 2048 + h4);
    float4 a = *y0, b = *y1;
    *(float4*)(out + (size_t)t * 2048 + h4) = make_float4(
        w0 * a.x + w1 * b.x, w0 * a.y + w1 * b.y,
        w0 * a.z + w1 * b.z, w0 * a.w + w1 * b.w);
}

// ---------------- entry ---------------------------------------------------------
extern "C" void kernel_launch(void* const* d_in, const int* in_sizes, int n_in,
                              void* d_out, int out_size) {
    const float* x   = (const float*)d_in[0];
    const int*   ids = (const int*)d_in[1];
    const float* tw  = (const float*)d_in[2];
    const float* w13 = (const float*)d_in[3];
    const float* s13 = (const float*)d_in[4];
    const float* w2  = (const float*)d_in[5];
    const float* s2  = (const float*)d_in[6];
    float* out = (float*)d_out;

    cudaFuncSetAttribute(mma_gemm<2048, true>,  cudaFuncAttributeMaxDynamicSharedMemorySize, SMEM_DYN);
    cudaFuncSetAttribute(mma_gemm<1024, false>, cudaFuncAttributeMaxDynamicSharedMemorySize, SMEM_DYN);

    route_kernel<<<1, NPAIRS>>>(ids);
    gather_kernel<<<NEXP * 512, 256>>>(x);

    dim3 grid(16, 8, NEXP);
    mma_gemm<2048, true><<<grid, 256, SMEM_DYN>>>(w13, s13);   // gate_up + silu fused
    mma_gemm<1024, false><<<grid, 256, SMEM_DYN>>>(w2, s2);    // down proj

    combine_kernel<<<(NTOK * 2048 / 4) / 256, 256>>>(tw, out);
}

// round 8
// speedup vs baseline: 1.2217x; 1.2217x over previous
#include <cuda_runtime.h>
#include <cuda_fp16.h>
#include <cstdint>

#define NTOK   256
#define NPAIRS 512
#define NEXP   8

// ---------------- scratch (device globals) ----------------------------------
__device__ int    g_cnt[NEXP];
__device__ int    g_pairs[NEXP][NPAIRS];
__device__ int    g_pos[NPAIRS];
__device__ __align__(16) __half g_Ah  [NEXP * 512 * 2048];   // gathered x rows, fp16
__device__ __align__(16) __half g_actE[NEXP * 512 * 1024];   // silu(gate)*up, fp16
__device__ float  g_yE  [NEXP * 512 * 2048];                 // GEMM2 out

// ---------------- helpers ----------------------------------------------------
__device__ __forceinline__ uint32_t smem_u32(const void* p) {
    uint32_t a;
    asm("{ .reg .u64 t; cvta.to.shared.u64 t, %1; cvt.u32.u64 %0, t; }" : "=r"(a) : "l"(p));
    return a;
}
__device__ __forceinline__ uint32_t pack_h2(float lo, float hi) {
    uint32_t r;
    asm("cvt.rn.f16x2.f32 %0, %1, %2;" : "=r"(r) : "f"(hi), "f"(lo));
    return r;
}
__device__ __forceinline__ void cpa16(uint32_t dst, const void* src) {
    asm volatile("cp.async.cg.shared.global [%0], [%1], 16;" :: "r"(dst), "l"(src));
}
#define CP_COMMIT() asm volatile("cp.async.commit_group;" ::: "memory")
#define CP_WAIT0()  asm volatile("cp.async.wait_group 0;" ::: "memory")

__device__ __forceinline__ void sts128(uint32_t a, uint32_t x, uint32_t y, uint32_t z, uint32_t w) {
    asm volatile("st.shared.v4.b32 [%0], {%1, %2, %3, %4};" :: "r"(a), "r"(x), "r"(y), "r"(z), "r"(w) : "memory");
}
__device__ __forceinline__ void ldsm4(uint32_t& r0, uint32_t& r1, uint32_t& r2, uint32_t& r3, uint32_t a) {
    asm volatile("ldmatrix.sync.aligned.m8n8.x4.shared.b16 {%0,%1,%2,%3}, [%4];"
                 : "=r"(r0), "=r"(r1), "=r"(r2), "=r"(r3) : "r"(a));
}
__device__ __forceinline__ void ldsm2(uint32_t& r0, uint32_t& r1, uint32_t a) {
    asm volatile("ldmatrix.sync.aligned.m8n8.x2.shared.b16 {%0,%1}, [%2];"
                 : "=r"(r0), "=r"(r1) : "r"(a));
}
__device__ __forceinline__ void mma16(float* c, const uint32_t* a, const uint32_t* b) {
    asm volatile("mma.sync.aligned.m16n8k16.row.col.f32.f16.f16.f32 "
                 "{%0,%1,%2,%3}, {%4,%5,%6,%7}, {%8,%9}, {%0,%1,%2,%3};"
                 : "+f"(c[0]), "+f"(c[1]), "+f"(c[2]), "+f"(c[3])
                 : "r"(a[0]), "r"(a[1]), "r"(a[2]), "r"(a[3]), "r"(b[0]), "r"(b[1]));
}

// ---------------- routing ----------------------------------------------------
__global__ void route_kernel(const int* __restrict__ ids) {
    int tid = threadIdx.x;
    if (tid < NEXP) g_cnt[tid] = 0;
    __syncthreads();
    int e   = ids[tid] & 7;
    int pos = atomicAdd(&g_cnt[e], 1);
    g_pairs[e][pos] = tid;
    g_pos[tid] = e * 512 + pos;
}

// ---------------- gather x rows into padded fp16 A ----------------------------
__global__ void gather_kernel(const float* __restrict__ x) {
    int bid = blockIdx.x;               // (e, m)
    int e = bid >> 9, m = bid & 511;
    int cnt = g_cnt[e];
    int lim = (cnt + 63) & ~63;
    if (m >= lim) return;
    uint4* dst = (uint4*)(g_Ah + ((size_t)e * 512 + m) * 2048);
    int tid = threadIdx.x;
    if (m < cnt) {
        int p = g_pairs[e][m];
        const float4* src = (const float4*)(x + (size_t)(p >> 1) * 2048) + tid * 2;
        float4 v0 = src[0], v1 = src[1];
        uint4 o;
        o.x = pack_h2(v0.x, v0.y); o.y = pack_h2(v0.z, v0.w);
        o.z = pack_h2(v1.x, v1.y); o.w = pack_h2(v1.z, v1.w);
        dst[tid] = o;
    } else {
        dst[tid] = make_uint4(0, 0, 0, 0);
    }
}

// ---------------- fp16 mma.sync GEMM -------------------------------------------
// BM=64, BN=64, BK=64; 256 threads; warps 4(m) x 2(n), warp tile 16x32.
// SMEM: A 2 stages x 64 rows x 144B; B(fp16) 2 stages x 64 rows x 144B = 36864 B.
// B weights: LDG fp32 (distance-2 register staging) -> scale -> cvt fp16 -> STS.
// G1 (n0 = bx*32): B rows 0-31 = gate (w13 row n0+r), 32-63 = up (w13 1024+n0+r-32);
//   epilogue computes silu(gate)*up -> g_actE fp16 (no act kernel).
// G2 (n0 = bx*64): plain 64-row tile of w2 -> g_yE fp32.
#define SMEM_DYN 36864

template<int KTOT, bool G1>
__global__ void __launch_bounds__(256, 2) mma_gemm(
    const float* __restrict__ Ball,
    const float* __restrict__ Sall)
{
    constexpr int KS = KTOT / 64;

    const int e   = blockIdx.z;
    const int cnt = g_cnt[e];
    const int m0  = blockIdx.y << 6;
    if (m0 >= cnt) return;
    const int n0  = G1 ? (blockIdx.x << 5) : (blockIdx.x << 6);

    const __half* Ah = (G1 ? g_Ah : g_actE) + ((size_t)e * 512 + m0) * KTOT;

    extern __shared__ float dsm[];
    const uint32_t sb = smem_u32(dsm);

    const int tid  = threadIdx.x;
    const int lane = tid & 31, w = tid >> 5;
    const int warpM = (w & 3) << 4;     // 0,16,32,48
    const int warpN = (w >> 2) << 5;    // 0,32

    // loader geometry: thread owns one row (tid>>2) and quarter (tid&3)
    const int row = tid >> 2, c4 = tid & 3;
    const __half* Asrc = Ah + (size_t)row * KTOT + c4 * 16;
    const uint32_t adst = sb + (uint32_t)(row * 144 + c4 * 32);

    const int bn = G1 ? ((row < 32) ? (n0 + row) : (1024 + n0 + row - 32))
                      : (n0 + row);
    const float* Bsrc = Ball + ((size_t)e * 2048 + bn) * KTOT + c4 * 16;
    const uint32_t bdst = sb + 18432u + (uint32_t)(row * 144 + c4 * 32);
    const float* Sme = Sall
        + ((size_t)e * 16 + (G1 ? ((row < 32) ? (n0 >> 7) : (8 + (n0 >> 7))) : (n0 >> 7)))
          * (KTOT / 128);

    // ldmatrix fragment bases (144B rows -> conflict-free)
    const int l2 = lane & 15;
    const uint32_t aFB = (uint32_t)((warpM + l2) * 144 + (lane >> 4) * 16);
    const uint32_t bFB = (uint32_t)((warpN + (l2 & 7)) * 144 + ((l2 >> 3) & 1) * 16);

    float acc[4][4] = {};
    float4 bst[2][4];

    auto ldgB = [&](int st, float4* v) {
        const float* p = Bsrc + st * 64;
        v[0] = *(const float4*)(p);     v[1] = *(const float4*)(p + 4);
        v[2] = *(const float4*)(p + 8); v[3] = *(const float4*)(p + 12);
    };
    auto stsB = [&](const float4* v, int buf, float sc) {
        uint32_t d = bdst + (uint32_t)(buf * 9216);
        sts128(d,      pack_h2(v[0].x * sc, v[0].y * sc), pack_h2(v[0].z * sc, v[0].w * sc),
                       pack_h2(v[1].x * sc, v[1].y * sc), pack_h2(v[1].z * sc, v[1].w * sc));
        sts128(d + 16, pack_h2(v[2].x * sc, v[2].y * sc), pack_h2(v[2].z * sc, v[2].w * sc),
                       pack_h2(v[3].x * sc, v[3].y * sc), pack_h2(v[3].z * sc, v[3].w * sc));
    };
    auto cpaA = [&](int st, int buf) {
        uint32_t d = adst + (uint32_t)(buf * 9216);
        cpa16(d,      Asrc + st * 64);
        cpa16(d + 16, Asrc + st * 64 + 8);
    };

    // -------- prologue --------
    ldgB(0, bst[0]);
    cpaA(0, 0); CP_COMMIT();
    ldgB(1, bst[1]);
    stsB(bst[0], 0, Sme[0]);
    CP_WAIT0();
    __syncthreads();

    // -------- main loop --------
#pragma unroll 2
    for (int s = 0; s < KS; s++) {
        if (s + 2 < KS) ldgB(s + 2, bst[s & 1]);        // dist-2 staging
        if (s + 1 < KS) {
            cpaA(s + 1, (s + 1) & 1);
            stsB(bst[(s + 1) & 1], (s + 1) & 1, Sme[(s + 1) >> 1]);
        }
        CP_COMMIT();

        const uint32_t aS = sb + (uint32_t)((s & 1) * 9216);
        const uint32_t bS = sb + 18432u + (uint32_t)((s & 1) * 9216);
#pragma unroll
        for (int ss = 0; ss < 4; ss++) {
            uint32_t af[4], bf[4][2];
            ldsm4(af[0], af[1], af[2], af[3], aS + aFB + (uint32_t)(ss * 32));
#pragma unroll
            for (int nt = 0; nt < 4; nt++)
                ldsm2(bf[nt][0], bf[nt][1], bS + bFB + (uint32_t)(nt * 1152 + ss * 32));
#pragma unroll
            for (int nt = 0; nt < 4; nt++)
                mma16(acc[nt], af, bf[nt]);
        }

        CP_WAIT0();
        __syncthreads();
    }

    // -------- epilogue --------
    const int rr = lane >> 2, cc = (lane & 3) << 1;
    if (!G1) {
        float* Cb = g_yE + ((size_t)e * 512 + m0) * 2048 + n0;
#pragma unroll
        for (int nt = 0; nt < 4; nt++) {
            float* p0 = Cb + (size_t)(warpM + rr) * 2048 + warpN + nt * 8 + cc;
            *(float2*)p0 = make_float2(acc[nt][0], acc[nt][1]);
            *(float2*)(p0 + 8 * 2048) = make_float2(acc[nt][2], acc[nt][3]);
        }
    } else {
        // fused silu(gate)*up; up warps (warpN=32, B rows 32-63) stage via smem
        float* ups = dsm;               // 64 rows x 36 floats (9216 B, reuses ring)
        if (w >= 4) {
#pragma unroll
            for (int nt = 0; nt < 4; nt++) {
                int col = nt * 8 + cc;
                *(float2*)(ups + (warpM + rr) * 36 + col)     = make_float2(acc[nt][0], acc[nt][1]);
                *(float2*)(ups + (warpM + 8 + rr) * 36 + col) = make_float2(acc[nt][2], acc[nt][3]);
            }
        }
        __syncthreads();
        if (w < 4) {
            __half* act = g_actE + ((size_t)e * 512 + m0) * 1024 + n0;
#pragma unroll
            for (int nt = 0; nt < 4; nt++) {
                int col = nt * 8 + cc;
                float2 u0 = *(float2*)(ups + (warpM + rr) * 36 + col);
                float2 u1 = *(float2*)(ups + (warpM + 8 + rr) * 36 + col);
                float g0 = acc[nt][0], g1 = acc[nt][1];
                float g2 = acc[nt][2], g3 = acc[nt][3];
                float a0 = g0 / (1.f + __expf(-g0)) * u0.x;
                float a1 = g1 / (1.f + __expf(-g1)) * u0.y;
                float a2 = g2 / (1.f + __expf(-g2)) * u1.x;
                float a3 = g3 / (1.f + __expf(-g3)) * u1.y;
                *(uint32_t*)(act + (size_t)(warpM + rr) * 1024 + col)     = pack_h2(a0, a1);
                *(uint32_t*)(act + (size_t)(warpM + 8 + rr) * 1024 + col) = pack_h2(a2, a3);
            }
        }
    }
}

// ---------------- combine -------------------------------------------------------
__global__ void combine_kernel(const float* __restrict__ tw,
                               float* __restrict__ out) {
    int idx = blockIdx.x * 256 + threadIdx.x;     // over 256*2048/4
    int t  = idx >> 9;
    int h4 = (idx & 511) << 2;
    float w0 = tw[2 * t + 0], w1 = tw[2 * t + 1];
    const float4* y0 = (const float4*)(g_yE + (size_t)g_pos[2 * t + 0] * 2048 + h4);
    const float4* y1 = (const float4*)(g_yE + (size_t)g_pos[2 * t + 1] * 2048 + h4);
    float4 a = *y0, b = *y1;
    *(float4*)(out + (size_t)t * 2048 + h4) = make_float4(
        w0 * a.x + w1 * b.x, w0 * a.y + w1 * b.y,
        w0 * a.z + w1 * b.z, w0 * a.w + w1 * b.w);
}

// ---------------- entry ---------------------------------------------------------
extern "C" void kernel_launch(void* const* d_in, const int* in_sizes, int n_in,
                              void* d_out, int out_size) {
    const float* x   = (const float*)d_in[0];
    const int*   ids = (const int*)d_in[1];
    const float* tw  = (const float*)d_in[2];
    const float* w13 = (const float*)d_in[3];
    const float* s13 = (const float*)d_in[4];
    const float* w2  = (const float*)d_in[5];
    const float* s2  = (const float*)d_in[6];
    float* out = (float*)d_out;

    cudaFuncSetAttribute(mma_gemm<2048, true>,  cudaFuncAttributeMaxDynamicSharedMemorySize, SMEM_DYN);
    cudaFuncSetAttribute(mma_gemm<1024, false>, cudaFuncAttributeMaxDynamicSharedMemorySize, SMEM_DYN);

    route_kernel<<<1, NPAIRS>>>(ids);
    gather_kernel<<<NEXP * 512, 256>>>(x);

    dim3 grid(32, 8, NEXP);
    mma_gemm<2048, true><<<grid, 256, SMEM_DYN>>>(w13, s13);   // gate_up + silu fused
    mma_gemm<1024, false><<<grid, 256, SMEM_DYN>>>(w2, s2);    // down proj

    combine_kernel<<<(NTOK * 2048 / 4) / 256, 256>>>(tw, out);
}

// round 9
// speedup vs baseline: 1.2856x; 1.0523x over previous
#include <cuda_runtime.h>
#include <cstdint>

#define NTOK   256
#define NPAIRS 512
#define NEXP   8

// ---------------- scratch (device globals) ----------------------------------
__device__ int   g_cnt[NEXP];
__device__ int   g_pairs[NEXP][NPAIRS];
__device__ int   g_pos[NPAIRS];
__device__ __align__(16) float g_Apad[NEXP * 512 * 2048];   // gathered x rows, tf32(rna), zero-padded
__device__ __align__(16) float g_actE[NEXP * 512 * 1024];   // silu(gate)*up, tf32(rna)
__device__ float g_yE  [NEXP * 512 * 2048];                 // GEMM2 out

// ---------------- helpers ----------------------------------------------------
__device__ __forceinline__ uint32_t smem_u32(const void* p) {
    uint32_t a;
    asm("{ .reg .u64 t; cvta.to.shared.u64 t, %1; cvt.u32.u64 %0, t; }" : "=r"(a) : "l"(p));
    return a;
}
__device__ __forceinline__ float f2tf32f(float x) {
    uint32_t u; asm("cvt.rna.tf32.f32 %0, %1;" : "=r"(u) : "f"(x));
    return __uint_as_float(u);
}
__device__ __forceinline__ void cpa16(uint32_t dst, const void* src) {
    asm volatile("cp.async.cg.shared.global [%0], [%1], 16;" :: "r"(dst), "l"(src));
}
#define CP_COMMIT() asm volatile("cp.async.commit_group;" ::: "memory")
#define CP_WAIT2()  asm volatile("cp.async.wait_group 2;" ::: "memory")

__device__ __forceinline__ void ldsm4(uint32_t& r0, uint32_t& r1, uint32_t& r2, uint32_t& r3, uint32_t a) {
    asm volatile("ldmatrix.sync.aligned.m8n8.x4.shared.b16 {%0,%1,%2,%3}, [%4];"
                 : "=r"(r0), "=r"(r1), "=r"(r2), "=r"(r3) : "r"(a));
}
__device__ __forceinline__ void ldsm2(uint32_t& r0, uint32_t& r1, uint32_t a) {
    asm volatile("ldmatrix.sync.aligned.m8n8.x2.shared.b16 {%0,%1}, [%2];"
                 : "=r"(r0), "=r"(r1) : "r"(a));
}
__device__ __forceinline__ void mma_tf32(float* c, const uint32_t* a, uint32_t b0, uint32_t b1) {
    asm volatile("mma.sync.aligned.m16n8k8.row.col.f32.tf32.tf32.f32 "
                 "{%0,%1,%2,%3}, {%4,%5,%6,%7}, {%8,%9}, {%0,%1,%2,%3};"
                 : "+f"(c[0]), "+f"(c[1]), "+f"(c[2]), "+f"(c[3])
                 : "r"(a[0]), "r"(a[1]), "r"(a[2]), "r"(a[3]), "r"(b0), "r"(b1));
}

// ---------------- routing ----------------------------------------------------
__global__ void route_kernel(const int* __restrict__ ids) {
    int tid = threadIdx.x;
    if (tid < NEXP) g_cnt[tid] = 0;
    __syncthreads();
    int e   = ids[tid] & 7;
    int pos = atomicAdd(&g_cnt[e], 1);
    g_pairs[e][pos] = tid;
    g_pos[tid] = e * 512 + pos;
}

// ---------------- gather x rows into padded tf32 A ----------------------------
__global__ void gather_kernel(const float* __restrict__ x) {
    int bid = blockIdx.x;               // (e, m)
    int e = bid >> 9, m = bid & 511;
    int cnt = g_cnt[e];
    int lim = (cnt + 63) & ~63;
    if (m >= lim) return;
    float4* dst = (float4*)(g_Apad + ((size_t)e * 512 + m) * 2048);
    if (m < cnt) {
        int p = g_pairs[e][m];
        const float4* src = (const float4*)(x + (size_t)(p >> 1) * 2048);
#pragma unroll
        for (int i = 0; i < 2; i++) {
            float4 v = src[threadIdx.x + 256 * i];
            dst[threadIdx.x + 256 * i] = make_float4(f2tf32f(v.x), f2tf32f(v.y),
                                                     f2tf32f(v.z), f2tf32f(v.w));
        }
    } else {
#pragma unroll
        for (int i = 0; i < 2; i++)
            dst[threadIdx.x + 256 * i] = make_float4(0.f, 0.f, 0.f, 0.f);
    }
}

// ---------------- tf32 mma.sync GEMM, full cp.async ring ----------------------
// BM=64, BN=64, BK=32; 256 threads; warps 4(m) x 2(n), warp tile 16x32.
// 4-stage SMEM ring: stage = { A fp32 64x(32+4pad), B raw fp32 64x(32+4pad) } = 18432 B.
// B is NEVER touched by ALU: cp.async in, ldmatrix out, tf32 mma on raw bits
// (truncation to tf32; mean bias compensated by (1+2^-12) folded into scale).
// Dequant scale applied on accumulator: final = fma(sc, part, final) per stage.
// G1 (n0 = bx*32): B rows 0-31 = gate (w13 n0+r), 32-63 = up (w13 1024+n0+r-32);
//   epilogue silu(gate)*up -> g_actE (fp32, rna-tf32).
// G2 (n0 = bx*64): plain 64-row w2 tile -> g_yE fp32.
#define STG_B 18432u
#define SMEM_DYN (4 * 18432)            // 73728 B -> 2 CTAs/SM

template<int KTOT, bool G1>
__global__ void __launch_bounds__(256, 2) mma_gemm(
    const float* __restrict__ Ball,
    const float* __restrict__ Sall)
{
    constexpr int KS = KTOT / 32;
    constexpr int KB = KTOT / 128;

    const int e   = blockIdx.z;
    const int cnt = g_cnt[e];
    const int m0  = blockIdx.y << 6;
    if (m0 >= cnt) return;
    const int n0  = G1 ? (blockIdx.x << 5) : (blockIdx.x << 6);

    const float* Ag = (G1 ? g_Apad : g_actE) + ((size_t)e * 512 + m0) * KTOT;

    extern __shared__ float dsm[];
    const uint32_t sb = smem_u32(dsm);

    const int tid  = threadIdx.x;
    const int lane = tid & 31, w = tid >> 5;
    const int warpM = (w & 3) << 4;     // 0,16,32,48
    const int ng    = w >> 2;           // 0 or 1 (n-group)
    const int warpN = ng << 5;          // 0 or 32

    // loader geometry: thread owns 16B granule g of rows r1 (0-31) and r2 (32-63)
    const int r1 = tid >> 3, g4 = tid & 7;
    const int r2 = r1 + 32;
    const float* As1 = Ag + (size_t)r1 * KTOT + g4 * 4;
    const float* As2 = Ag + (size_t)r2 * KTOT + g4 * 4;
    const int bn1 = n0 + r1;                                     // gate rows (G1) / rows 0-31 (G2)
    const int bn2 = G1 ? (1024 + n0 + (r2 - 32)) : (n0 + r2);    // up rows (G1)
    const float* Bs1 = Ball + ((size_t)e * 2048 + bn1) * KTOT + g4 * 4;
    const float* Bs2 = Ball + ((size_t)e * 2048 + bn2) * KTOT + g4 * 4;
    const uint32_t d1 = (uint32_t)(r1 * 144 + g4 * 16);
    const uint32_t d2 = d1 + 32 * 144;

    // per-warp dequant scale row (+ tf32-truncation bias compensation)
    const float* Sme = Sall
        + ((size_t)e * 16 + (G1 ? (ng * 8 + (n0 >> 7)) : (n0 >> 7))) * KB;

    // ldmatrix fragment bases (144B rows, validated tf32 layout)
    const int l2 = lane & 15;
    const uint32_t aFB = (uint32_t)((warpM + (lane & 7) + ((lane >> 3) & 1) * 8) * 144
                                    + (lane >> 4) * 16);
    const uint32_t bFB = (uint32_t)((warpN + (l2 & 7)) * 144 + ((l2 >> 3) & 1) * 16);

    float fa[4][4] = {};                // final (scaled) accumulators
    float pa[4][4] = {};                // per-k-block partials

    auto issue = [&](int s) {
        const uint32_t st = sb + (uint32_t)(s & 3) * STG_B;
        cpa16(st + d1,         As1 + s * 32);
        cpa16(st + d2,         As2 + s * 32);
        cpa16(st + 9216 + d1,  Bs1 + s * 32);
        cpa16(st + 9216 + d2,  Bs2 + s * 32);
    };

    // -------- prologue: 3 stages in flight --------
    issue(0); CP_COMMIT();
    issue(1); CP_COMMIT();
    issue(2); CP_COMMIT();

    // -------- main loop --------
#pragma unroll 4
    for (int s = 0; s < KS; s++) {
        CP_WAIT2();                     // stage s landed
        __syncthreads();
        if (s + 3 < KS) issue(s + 3);   // into buffer consumed at s-1 (sync'd)
        CP_COMMIT();

        const uint32_t aS = sb + (uint32_t)(s & 3) * STG_B;
        const uint32_t bS = aS + 9216;
#pragma unroll
        for (int ss = 0; ss < 4; ss++) {
            uint32_t af[4];
            ldsm4(af[0], af[1], af[2], af[3], aS + aFB + (uint32_t)(ss * 32));
#pragma unroll
            for (int nt = 0; nt < 4; nt++) {
                uint32_t b0, b1;
                ldsm2(b0, b1, bS + bFB + (uint32_t)(nt * 1152 + ss * 32));
                mma_tf32(pa[nt], af, b0, b1);
            }
        }

        const float sc = Sme[s >> 2] * 1.000244140625f;   // + truncation-bias comp
#pragma unroll
        for (int nt = 0; nt < 4; nt++)
#pragma unroll
            for (int i = 0; i < 4; i++) {
                fa[nt][i] = fmaf(sc, pa[nt][i], fa[nt][i]);
                pa[nt][i] = 0.f;
            }
    }

    // -------- epilogue --------
    const int rr = lane >> 2, cc = (lane & 3) << 1;
    if (!G1) {
        float* Cb = g_yE + ((size_t)e * 512 + m0) * 2048 + n0;
#pragma unroll
        for (int nt = 0; nt < 4; nt++) {
            float* p0 = Cb + (size_t)(warpM + rr) * 2048 + warpN + nt * 8 + cc;
            *(float2*)p0 = make_float2(fa[nt][0], fa[nt][1]);
            *(float2*)(p0 + 8 * 2048) = make_float2(fa[nt][2], fa[nt][3]);
        }
    } else {
        // fused silu(gate)*up; up warps (ng==1) stage via smem
        __syncthreads();
        float* ups = dsm;               // 64 rows x 36 floats (reuses ring)
        if (ng == 1) {
#pragma unroll
            for (int nt = 0; nt < 4; nt++) {
                int col = nt * 8 + cc;
                *(float2*)(ups + (warpM + rr) * 36 + col)     = make_float2(fa[nt][0], fa[nt][1]);
                *(float2*)(ups + (warpM + 8 + rr) * 36 + col) = make_float2(fa[nt][2], fa[nt][3]);
            }
        }
        __syncthreads();
        if (ng == 0) {
            float* act = g_actE + ((size_t)e * 512 + m0) * 1024 + n0;
#pragma unroll
            for (int nt = 0; nt < 4; nt++) {
                int col = nt * 8 + cc;
                float2 u0 = *(float2*)(ups + (warpM + rr) * 36 + col);
                float2 u1 = *(float2*)(ups + (warpM + 8 + rr) * 36 + col);
                float g0 = fa[nt][0], g1 = fa[nt][1];
                float g2 = fa[nt][2], g3 = fa[nt][3];
                float a0 = g0 / (1.f + __expf(-g0)) * u0.x;
                float a1 = g1 / (1.f + __expf(-g1)) * u0.y;
                float a2 = g2 / (1.f + __expf(-g2)) * u1.x;
                float a3 = g3 / (1.f + __expf(-g3)) * u1.y;
                *(float2*)(act + (size_t)(warpM + rr) * 1024 + col) =
                    make_float2(f2tf32f(a0), f2tf32f(a1));
                *(float2*)(act + (size_t)(warpM + 8 + rr) * 1024 + col) =
                    make_float2(f2tf32f(a2), f2tf32f(a3));
            }
        }
    }
}

// ---------------- combine -------------------------------------------------------
__global__ void combine_kernel(const float* __restrict__ tw,
                               float* __restrict__ out) {
    int idx = blockIdx.x * 256 + threadIdx.x;     // over 256*2048/4
    int t  = idx >> 9;
    int h4 = (idx & 511) << 2;
    float w0 = tw[2 * t + 0], w1 = tw[2 * t + 1];
    const float4* y0 = (const float4*)(g_yE + (size_t)g_pos[2 * t + 0] * 2048 + h4);
    const float4* y1 = (const float4*)(g_yE + (size_t)g_pos[2 * t + 1] * 2048 + h4);
    float4 a = *y0, b = *y1;
    *(float4*)(out + (size_t)t * 2048 + h4) = make_float4(
        w0 * a.x + w1 * b.x, w0 * a.y + w1 * b.y,
        w0 * a.z + w1 * b.z, w0 * a.w + w1 * b.w);
}

// ---------------- entry ---------------------------------------------------------
extern "C" void kernel_launch(void* const* d_in, const int* in_sizes, int n_in,
                              void* d_out, int out_size) {
    const float* x   = (const float*)d_in[0];
    const int*   ids = (const int*)d_in[1];
    const float* tw  = (const float*)d_in[2];
    const float* w13 = (const float*)d_in[3];
    const float* s13 = (const float*)d_in[4];
    const float* w2  = (const float*)d_in[5];
    const float* s2  = (const float*)d_in[6];
    float* out = (float*)d_out;

    cudaFuncSetAttribute(mma_gemm<2048, true>,  cudaFuncAttributeMaxDynamicSharedMemorySize, SMEM_DYN);
    cudaFuncSetAttribute(mma_gemm<1024, false>, cudaFuncAttributeMaxDynamicSharedMemorySize, SMEM_DYN);

    route_kernel<<<1, NPAIRS>>>(ids);
    gather_kernel<<<NEXP * 512, 256>>>(x);

    dim3 grid(32, 8, NEXP);
    mma_gemm<2048, true><<<grid, 256, SMEM_DYN>>>(w13, s13);   // gate_up + silu fused
    mma_gemm<1024, false><<<grid, 256, SMEM_DYN>>>(w2, s2);    // down proj

    combine_kernel<<<(NTOK * 2048 / 4) / 256, 256>>>(tw, out);
}

// round 10
// speedup vs baseline: 1.5824x; 1.2309x over previous
#include <cuda_runtime.h>
#include <cuda_fp16.h>
#include <cstdint>

#define NTOK   256
#define NPAIRS 512
#define NEXP   8

// ---------------- scratch (device globals) ----------------------------------
__device__ int    g_cnt[NEXP];
__device__ int    g_pairs[NEXP][NPAIRS];
__device__ int    g_pos[NPAIRS];
__device__ __align__(16) __half g_Ah  [NEXP * 512 * 2048];   // gathered x rows, fp16
__device__ __align__(16) __half g_actE[NEXP * 512 * 1024];   // silu(gate)*up, fp16
__device__ float  g_gu1[NEXP * 512 * 2048];  // GEMM1 partial, k-half 0 (gate|up packed)
__device__ float  g_gu2[NEXP * 512 * 2048];  // GEMM1 partial, k-half 1
__device__ float  g_y1 [NEXP * 512 * 2048];  // GEMM2 partial, k-half 0
__device__ float  g_y2 [NEXP * 512 * 2048];  // GEMM2 partial, k-half 1

// ---------------- helpers ----------------------------------------------------
__device__ __forceinline__ uint32_t smem_u32(const void* p) {
    uint32_t a;
    asm("{ .reg .u64 t; cvta.to.shared.u64 t, %1; cvt.u32.u64 %0, t; }" : "=r"(a) : "l"(p));
    return a;
}
__device__ __forceinline__ uint32_t pack_h2(float lo, float hi) {
    uint32_t r;
    asm("cvt.rn.f16x2.f32 %0, %1, %2;" : "=r"(r) : "f"(hi), "f"(lo));
    return r;
}
__device__ __forceinline__ void cpa16(uint32_t dst, const void* src) {
    asm volatile("cp.async.cg.shared.global [%0], [%1], 16;" :: "r"(dst), "l"(src));
}
#define CP_COMMIT() asm volatile("cp.async.commit_group;" ::: "memory")
#define CP_WAIT0()  asm volatile("cp.async.wait_group 0;" ::: "memory")

__device__ __forceinline__ void sts128(uint32_t a, uint32_t x, uint32_t y, uint32_t z, uint32_t w) {
    asm volatile("st.shared.v4.b32 [%0], {%1, %2, %3, %4};" :: "r"(a), "r"(x), "r"(y), "r"(z), "r"(w) : "memory");
}
__device__ __forceinline__ void ldsm4(uint32_t& r0, uint32_t& r1, uint32_t& r2, uint32_t& r3, uint32_t a) {
    asm volatile("ldmatrix.sync.aligned.m8n8.x4.shared.b16 {%0,%1,%2,%3}, [%4];"
                 : "=r"(r0), "=r"(r1), "=r"(r2), "=r"(r3) : "r"(a));
}
__device__ __forceinline__ void ldsm2(uint32_t& r0, uint32_t& r1, uint32_t a) {
    asm volatile("ldmatrix.sync.aligned.m8n8.x2.shared.b16 {%0,%1}, [%2];"
                 : "=r"(r0), "=r"(r1) : "r"(a));
}
__device__ __forceinline__ void mma16(float* c, const uint32_t* a, const uint32_t* b) {
    asm volatile("mma.sync.aligned.m16n8k16.row.col.f32.f16.f16.f32 "
                 "{%0,%1,%2,%3}, {%4,%5,%6,%7}, {%8,%9}, {%0,%1,%2,%3};"
                 : "+f"(c[0]), "+f"(c[1]), "+f"(c[2]), "+f"(c[3])
                 : "r"(a[0]), "r"(a[1]), "r"(a[2]), "r"(a[3]), "r"(b[0]), "r"(b[1]));
}

// ---------------- routing ----------------------------------------------------
__global__ void route_kernel(const int* __restrict__ ids) {
    int tid = threadIdx.x;
    if (tid < NEXP) g_cnt[tid] = 0;
    __syncthreads();
    int e   = ids[tid] & 7;
    int pos = atomicAdd(&g_cnt[e], 1);
    g_pairs[e][pos] = tid;
    g_pos[tid] = e * 512 + pos;
}

// ---------------- gather x rows into padded fp16 A ----------------------------
__global__ void gather_kernel(const float* __restrict__ x) {
    int bid = blockIdx.x;               // (e, m)
    int e = bid >> 9, m = bid & 511;
    int cnt = g_cnt[e];
    int lim = (cnt + 63) & ~63;
    if (m >= lim) return;
    uint4* dst = (uint4*)(g_Ah + ((size_t)e * 512 + m) * 2048);
    int tid = threadIdx.x;
    if (m < cnt) {
        int p = g_pairs[e][m];
        const float4* src = (const float4*)(x + (size_t)(p >> 1) * 2048) + tid * 2;
        float4 v0 = src[0], v1 = src[1];
        uint4 o;
        o.x = pack_h2(v0.x, v0.y); o.y = pack_h2(v0.z, v0.w);
        o.z = pack_h2(v1.x, v1.y); o.w = pack_h2(v1.z, v1.w);
        dst[tid] = o;
    } else {
        dst[tid] = make_uint4(0, 0, 0, 0);
    }
}

// ---------------- fp16 mma.sync GEMM, split-K=2 --------------------------------
// BM=64, BN=128, BK=64; 256 threads; warps 2(m) x 4(n), warp tile 32x32.
// grid.z = 16: e = bz&7, khalf = bz>>3. Each half does K/2, writes its own
// partial buffer (bit-deterministic, no atomics). Identical mainloop to the
// proven round-6 kernel (dist-1 register-staged B, cp.async A).
// G1: B rows 0-63 = gate (w13 row n0+r), 64-127 = up (w13 1024+n0+r-64);
//     raw gate|up partials -> g_gu{1,2} (act kernel sums + silu).
// G2: plain BN=128 tile of w2 -> g_y{1,2}.
#define A_STGB 9216                     // 64 rows * 144B
#define B_STGB 18432                    // 128 rows * 144B
#define SMEM_DYN (2 * A_STGB + 2 * B_STGB)   // 55296

template<int KTOT, bool G1>
__global__ void __launch_bounds__(256, 2) mma_gemm(
    const float* __restrict__ Ball,
    const float* __restrict__ Sall)
{
    constexpr int KHALF = KTOT / 2;
    constexpr int KS = KHALF / 64;
    constexpr int KB = KTOT / 128;      // scale k-blocks (full K)

    const int bz  = blockIdx.z;
    const int e   = bz & 7;
    const int kh  = bz >> 3;
    const int cnt = g_cnt[e];
    const int m0  = blockIdx.y << 6;
    if (m0 >= cnt) return;
    const int n0  = G1 ? (blockIdx.x << 6) : (blockIdx.x << 7);

    const __half* Ah = (G1 ? g_Ah : g_actE)
                       + ((size_t)e * 512 + m0) * KTOT + (size_t)kh * KHALF;

    extern __shared__ float dsm[];
    const uint32_t sbase = smem_u32(dsm);

    const int tid  = threadIdx.x;
    const int lane = tid & 31, w = tid >> 5;
    const int warpM = (w & 1) << 5;     // 0 or 32
    const int warpN = (w >> 1) << 5;    // 0,32,64,96

    // loader geometry: 16B granules, 8 per 128B row chunk
    const int rowg  = tid >> 3;         // 0..31
    const int col16 = tid & 7;
    const uint32_t ldoff = (uint32_t)(rowg * 144 + col16 * 16);

    // B source pointers per granule (4 granules -> 128 rows), k-half offset
    const float* Bp[4];
#pragma unroll
    for (int i = 0; i < 4; i++) {
        int n = G1 ? ((i < 2) ? (n0 + rowg + 32 * i) : (1024 + n0 + rowg + 32 * (i - 2)))
                   : (n0 + rowg + 32 * i);
        Bp[i] = Ball + ((size_t)e * 2048 + n) * KTOT + (size_t)kh * KHALF + col16 * 8;
    }
    const float* Sg = Sall + ((size_t)e * 16 + (n0 >> 7)) * KB + kh * (KB / 2);
    const float* Su = G1 ? (Sall + ((size_t)e * 16 + 8 + (n0 >> 7)) * KB + kh * (KB / 2)) : Sg;

    // ldmatrix per-lane address bases
    const int l2 = lane & 15;
    const uint32_t aFragBase = (uint32_t)((warpM + (lane & 7) + ((lane >> 3) & 1) * 8) * 144
                                          + ((lane >> 4) & 1) * 16);
    const uint32_t bFragBase = (uint32_t)((warpN + (l2 & 7)) * 144 + ((l2 >> 3) & 1) * 16);

    float acc[2][4][4];
#pragma unroll
    for (int mt = 0; mt < 2; mt++)
#pragma unroll
        for (int nt = 0; nt < 4; nt++)
#pragma unroll
            for (int i = 0; i < 4; i++) acc[mt][nt][i] = 0.f;

    // -------- prologue: fill stage 0 --------
    {
#pragma unroll
        for (int i = 0; i < 2; i++)
            cpa16(sbase + ldoff + (uint32_t)(i * 4608),
                  Ah + (size_t)(rowg + 32 * i) * KTOT + col16 * 8);
        CP_COMMIT();
#pragma unroll
        for (int i = 0; i < 4; i++) {
            float sc = (G1 && i >= 2) ? Su[0] : Sg[0];
            float4 u = *(const float4*)(Bp[i]);
            float4 v = *(const float4*)(Bp[i] + 4);
            sts128(sbase + 2 * A_STGB + ldoff + (uint32_t)(i * 4608),
                   pack_h2(u.x * sc, u.y * sc), pack_h2(u.z * sc, u.w * sc),
                   pack_h2(v.x * sc, v.y * sc), pack_h2(v.z * sc, v.w * sc));
        }
        CP_WAIT0();
        __syncthreads();
    }

    // -------- main loop --------
    for (int ks = 0; ks < KS; ks++) {
        const int cur = ks & 1, nxt = cur ^ 1;
        const uint32_t aCur = sbase + (uint32_t)(cur * A_STGB);
        const uint32_t bCur = sbase + (uint32_t)(2 * A_STGB + cur * B_STGB);

        float4 bu[4], bv[4];
        float  sc[4];
        const bool more = (ks + 1 < KS);
        if (more) {
            const int kf = (ks + 1) * 64;
            const int kb = (ks + 1) >> 1;
            const uint32_t aNxt = sbase + (uint32_t)(nxt * A_STGB);
#pragma unroll
            for (int i = 0; i < 2; i++)
                cpa16(aNxt + ldoff + (uint32_t)(i * 4608),
                      Ah + (size_t)(rowg + 32 * i) * KTOT + kf + col16 * 8);
            CP_COMMIT();
#pragma unroll
            for (int i = 0; i < 4; i++) {
                bu[i] = *(const float4*)(Bp[i] + kf);
                bv[i] = *(const float4*)(Bp[i] + kf + 4);
                sc[i] = (G1 && i >= 2) ? Su[kb] : Sg[kb];
            }
        }

        // compute on cur: 4 k16 steps
#pragma unroll
        for (int s = 0; s < 4; s++) {
            uint32_t af[2][4], bf[4][2];
#pragma unroll
            for (int mt = 0; mt < 2; mt++)
                ldsm4(af[mt][0], af[mt][1], af[mt][2], af[mt][3],
                      aCur + aFragBase + (uint32_t)(mt * 16 * 144 + s * 32));
#pragma unroll
            for (int nt = 0; nt < 4; nt++)
                ldsm2(bf[nt][0], bf[nt][1],
                      bCur + bFragBase + (uint32_t)(nt * 8 * 144 + s * 32));
#pragma unroll
            for (int mt = 0; mt < 2; mt++)
#pragma unroll
                for (int nt = 0; nt < 4; nt++)
                    mma16(acc[mt][nt], af[mt], bf[nt]);
        }

        if (more) {
            const uint32_t bNxt = sbase + (uint32_t)(2 * A_STGB + nxt * B_STGB);
#pragma unroll
            for (int i = 0; i < 4; i++) {
                sts128(bNxt + ldoff + (uint32_t)(i * 4608),
                       pack_h2(bu[i].x * sc[i], bu[i].y * sc[i]),
                       pack_h2(bu[i].z * sc[i], bu[i].w * sc[i]),
                       pack_h2(bv[i].x * sc[i], bv[i].y * sc[i]),
                       pack_h2(bv[i].z * sc[i], bv[i].w * sc[i]));
            }
            CP_WAIT0();
        }
        __syncthreads();
    }

    // -------- epilogue: raw partial stores (no silu; summed later) --------
    const int rr = lane >> 2, cc = (lane & 3) << 1;
    if (!G1) {
        float* Cb = (kh ? g_y2 : g_y1) + ((size_t)e * 512 + m0) * 2048 + n0;
#pragma unroll
        for (int mt = 0; mt < 2; mt++)
#pragma unroll
            for (int nt = 0; nt < 4; nt++) {
                float* p0 = Cb + (size_t)(warpM + mt * 16 + rr) * 2048 + warpN + nt * 8 + cc;
                *(float2*)p0 = make_float2(acc[mt][nt][0], acc[mt][nt][1]);
                *(float2*)(p0 + 8 * 2048) = make_float2(acc[mt][nt][2], acc[mt][nt][3]);
            }
    } else {
        float* Cb = (kh ? g_gu2 : g_gu1) + ((size_t)e * 512 + m0) * 2048;
        // acc column c in 0..127 = B row: c<64 -> gate col n0+c; else up col 1024+n0+c-64
        const int cb = warpN + cc;
        const int col = (cb < 64) ? (n0 + cb) : (1024 + n0 + cb - 64);
#pragma unroll
        for (int mt = 0; mt < 2; mt++)
#pragma unroll
            for (int nt = 0; nt < 4; nt++) {
                float* p0 = Cb + (size_t)(warpM + mt * 16 + rr) * 2048 + col + nt * 8;
                *(float2*)p0 = make_float2(acc[mt][nt][0], acc[mt][nt][1]);
                *(float2*)(p0 + 8 * 2048) = make_float2(acc[mt][nt][2], acc[mt][nt][3]);
            }
    }
}

// ---------------- activation: silu(g1+g2) * (u1+u2) -> fp16 -------------------
__global__ void act_kernel() {
    int idx = blockIdx.x * 256 + threadIdx.x;     // over 8*512*1024/4
    int row = idx >> 8;
    int e = row >> 9, m = row & 511;
    int lim = (g_cnt[e] + 63) & ~63;
    if (m >= lim) return;
    int i4 = (idx & 255) << 2;
    const float* b1 = g_gu1 + (size_t)row * 2048;
    const float* b2 = g_gu2 + (size_t)row * 2048;
    float4 ga = *(const float4*)(b1 + i4);
    float4 gb = *(const float4*)(b2 + i4);
    float4 ua = *(const float4*)(b1 + 1024 + i4);
    float4 ub = *(const float4*)(b2 + 1024 + i4);
    float g0 = ga.x + gb.x, g1 = ga.y + gb.y, g2 = ga.z + gb.z, g3 = ga.w + gb.w;
    float u0 = ua.x + ub.x, u1 = ua.y + ub.y, u2 = ua.z + ub.z, u3 = ua.w + ub.w;
    float a0 = g0 / (1.f + __expf(-g0)) * u0;
    float a1 = g1 / (1.f + __expf(-g1)) * u1;
    float a2 = g2 / (1.f + __expf(-g2)) * u2;
    float a3 = g3 / (1.f + __expf(-g3)) * u3;
    uint2 o;
    o.x = pack_h2(a0, a1);
    o.y = pack_h2(a2, a3);
    *(uint2*)(g_actE + (size_t)row * 1024 + i4) = o;
}

// ---------------- combine: out = w0*(y1+y2)[p0] + w1*(y1+y2)[p1] ---------------
__global__ void combine_kernel(const float* __restrict__ tw,
                               float* __restrict__ out) {
    int idx = blockIdx.x * 256 + threadIdx.x;     // over 256*2048/4
    int t  = idx >> 9;
    int h4 = (idx & 511) << 2;
    float w0 = tw[2 * t + 0], w1 = tw[2 * t + 1];
    size_t r0 = (size_t)g_pos[2 * t + 0] * 2048 + h4;
    size_t r1 = (size_t)g_pos[2 * t + 1] * 2048 + h4;
    float4 a1 = *(const float4*)(g_y1 + r0);
    float4 a2 = *(const float4*)(g_y2 + r0);
    float4 b1 = *(const float4*)(g_y1 + r1);
    float4 b2 = *(const float4*)(g_y2 + r1);
    *(float4*)(out + (size_t)t * 2048 + h4) = make_float4(
        w0 * (a1.x + a2.x) + w1 * (b1.x + b2.x),
        w0 * (a1.y + a2.y) + w1 * (b1.y + b2.y),
        w0 * (a1.z + a2.z) + w1 * (b1.z + b2.z),
        w0 * (a1.w + a2.w) + w1 * (b1.w + b2.w));
}

// ---------------- entry ---------------------------------------------------------
extern "C" void kernel_launch(void* const* d_in, const int* in_sizes, int n_in,
                              void* d_out, int out_size) {
    const float* x   = (const float*)d_in[0];
    const int*   ids = (const int*)d_in[1];
    const float* tw  = (const float*)d_in[2];
    const float* w13 = (const float*)d_in[3];
    const float* s13 = (const float*)d_in[4];
    const float* w2  = (const float*)d_in[5];
    const float* s2  = (const float*)d_in[6];
    float* out = (float*)d_out;

    cudaFuncSetAttribute(mma_gemm<2048, true>,  cudaFuncAttributeMaxDynamicSharedMemorySize, SMEM_DYN);
    cudaFuncSetAttribute(mma_gemm<1024, false>, cudaFuncAttributeMaxDynamicSharedMemorySize, SMEM_DYN);

    route_kernel<<<1, NPAIRS>>>(ids);
    gather_kernel<<<NEXP * 512, 256>>>(x);

    dim3 grid(16, 8, 16);               // n-tiles x m-tiles x (expert + khalf*8)
    mma_gemm<2048, true><<<grid, 256, SMEM_DYN>>>(w13, s13);   // gate_up partials
    act_kernel<<<(NEXP * 512 * 1024 / 4) / 256, 256>>>();      // sum + silu -> fp16
    mma_gemm<1024, false><<<grid, 256, SMEM_DYN>>>(w2, s2);    // down-proj partials
    combine_kernel<<<(NTOK * 2048 / 4) / 256, 256>>>(tw, out); // sum + weighted mix
}

// round 11
// speedup vs baseline: 1.5942x; 1.0075x over previous
#include <cuda_runtime.h>
#include <cuda_fp16.h>
#include <cstdint>

#define NTOK   256
#define NPAIRS 512
#define NEXP   8

// ---------------- scratch (device globals) ----------------------------------
__device__ int    g_cnt[NEXP];
__device__ int    g_pairs[NEXP][NPAIRS];
__device__ int    g_pos[NPAIRS];
__device__ __align__(16) __half g_Ah  [NEXP * 512 * 2048];   // gathered x rows, fp16
__device__ __align__(16) __half g_actE[NEXP * 512 * 1024];   // silu(gate)*up, fp16
__device__ float  g_gu1[NEXP * 512 * 2048];  // GEMM1 partial, k-half 0 (gate|up packed)
__device__ float  g_gu2[NEXP * 512 * 2048];  // GEMM1 partial, k-half 1
__device__ float  g_y1 [NEXP * 512 * 2048];  // GEMM2 partial, k-half 0
__device__ float  g_y2 [NEXP * 512 * 2048];  // GEMM2 partial, k-half 1

// ---------------- helpers ----------------------------------------------------
__device__ __forceinline__ uint32_t smem_u32(const void* p) {
    uint32_t a;
    asm("{ .reg .u64 t; cvta.to.shared.u64 t, %1; cvt.u32.u64 %0, t; }" : "=r"(a) : "l"(p));
    return a;
}
__device__ __forceinline__ uint32_t pack_h2(float lo, float hi) {
    uint32_t r;
    asm("cvt.rn.f16x2.f32 %0, %1, %2;" : "=r"(r) : "f"(hi), "f"(lo));
    return r;
}
__device__ __forceinline__ void cpa16(uint32_t dst, const void* src) {
    asm volatile("cp.async.cg.shared.global [%0], [%1], 16;" :: "r"(dst), "l"(src));
}
__device__ __forceinline__ void pf_l2(const void* p) {
    asm volatile("prefetch.global.L2 [%0];" :: "l"(p));
}
#define CP_COMMIT() asm volatile("cp.async.commit_group;" ::: "memory")
#define CP_WAIT0()  asm volatile("cp.async.wait_group 0;" ::: "memory")

__device__ __forceinline__ void sts128(uint32_t a, uint32_t x, uint32_t y, uint32_t z, uint32_t w) {
    asm volatile("st.shared.v4.b32 [%0], {%1, %2, %3, %4};" :: "r"(a), "r"(x), "r"(y), "r"(z), "r"(w) : "memory");
}
__device__ __forceinline__ void ldsm4(uint32_t& r0, uint32_t& r1, uint32_t& r2, uint32_t& r3, uint32_t a) {
    asm volatile("ldmatrix.sync.aligned.m8n8.x4.shared.b16 {%0,%1,%2,%3}, [%4];"
                 : "=r"(r0), "=r"(r1), "=r"(r2), "=r"(r3) : "r"(a));
}
__device__ __forceinline__ void ldsm2(uint32_t& r0, uint32_t& r1, uint32_t a) {
    asm volatile("ldmatrix.sync.aligned.m8n8.x2.shared.b16 {%0,%1}, [%2];"
                 : "=r"(r0), "=r"(r1) : "r"(a));
}
__device__ __forceinline__ void mma16(float* c, const uint32_t* a, const uint32_t* b) {
    asm volatile("mma.sync.aligned.m16n8k16.row.col.f32.f16.f16.f32 "
                 "{%0,%1,%2,%3}, {%4,%5,%6,%7}, {%8,%9}, {%0,%1,%2,%3};"
                 : "+f"(c[0]), "+f"(c[1]), "+f"(c[2]), "+f"(c[3])
                 : "r"(a[0]), "r"(a[1]), "r"(a[2]), "r"(a[3]), "r"(b[0]), "r"(b[1]));
}

// ---------------- routing ----------------------------------------------------
__global__ void route_kernel(const int* __restrict__ ids) {
    int tid = threadIdx.x;
    if (tid < NEXP) g_cnt[tid] = 0;
    __syncthreads();
    int e   = ids[tid] & 7;
    int pos = atomicAdd(&g_cnt[e], 1);
    g_pairs[e][pos] = tid;
    g_pos[tid] = e * 512 + pos;
}

// ---------------- gather x rows into padded fp16 A ----------------------------
__global__ void gather_kernel(const float* __restrict__ x) {
    int bid = blockIdx.x;               // (e, m)
    int e = bid >> 9, m = bid & 511;
    int cnt = g_cnt[e];
    int lim = (cnt + 63) & ~63;
    if (m >= lim) return;
    uint4* dst = (uint4*)(g_Ah + ((size_t)e * 512 + m) * 2048);
    int tid = threadIdx.x;
    if (m < cnt) {
        int p = g_pairs[e][m];
        const float4* src = (const float4*)(x + (size_t)(p >> 1) * 2048) + tid * 2;
        float4 v0 = src[0], v1 = src[1];
        uint4 o;
        o.x = pack_h2(v0.x, v0.y); o.y = pack_h2(v0.z, v0.w);
        o.z = pack_h2(v1.x, v1.y); o.w = pack_h2(v1.z, v1.w);
        dst[tid] = o;
    } else {
        dst[tid] = make_uint4(0, 0, 0, 0);
    }
}

// ---------------- fp16 mma.sync GEMM, split-K=2 + L2 prefetch ------------------
// BM=64, BN=128, BK=64; 256 threads; warps 2(m) x 4(n), warp tile 32x32.
// grid.z = 16: e = bz&7, khalf = bz>>3. Deterministic partial buffers.
// prefetch.global.L2 pulls stage s+3 (A and B) while stage s computes, so the
// dist-1 LDG/cp.async at stage s+2 hits L2 (~250cyc) instead of DRAM (~600cyc).
#define A_STGB 9216                     // 64 rows * 144B
#define B_STGB 18432                    // 128 rows * 144B
#define SMEM_DYN (2 * A_STGB + 2 * B_STGB)   // 55296

template<int KTOT, bool G1>
__global__ void __launch_bounds__(256, 2) mma_gemm(
    const float* __restrict__ Ball,
    const float* __restrict__ Sall)
{
    constexpr int KHALF = KTOT / 2;
    constexpr int KS = KHALF / 64;
    constexpr int KB = KTOT / 128;      // scale k-blocks (full K)

    const int bz  = blockIdx.z;
    const int e   = bz & 7;
    const int kh  = bz >> 3;
    const int cnt = g_cnt[e];
    const int m0  = blockIdx.y << 6;
    if (m0 >= cnt) return;
    const int n0  = G1 ? (blockIdx.x << 6) : (blockIdx.x << 7);

    const __half* Ah = (G1 ? g_Ah : g_actE)
                       + ((size_t)e * 512 + m0) * KTOT + (size_t)kh * KHALF;

    extern __shared__ float dsm[];
    const uint32_t sbase = smem_u32(dsm);

    const int tid  = threadIdx.x;
    const int lane = tid & 31, w = tid >> 5;
    const int warpM = (w & 1) << 5;     // 0 or 32
    const int warpN = (w >> 1) << 5;    // 0,32,64,96

    // loader geometry: 16B granules, 8 per 128B row chunk
    const int rowg  = tid >> 3;         // 0..31
    const int col16 = tid & 7;
    const uint32_t ldoff = (uint32_t)(rowg * 144 + col16 * 16);
    const bool pfth = (col16 & 3) == 0; // one prefetcher per 128B line

    // B source pointers per granule (4 granules -> 128 rows), k-half offset
    const float* Bp[4];
#pragma unroll
    for (int i = 0; i < 4; i++) {
        int n = G1 ? ((i < 2) ? (n0 + rowg + 32 * i) : (1024 + n0 + rowg + 32 * (i - 2)))
                   : (n0 + rowg + 32 * i);
        Bp[i] = Ball + ((size_t)e * 2048 + n) * KTOT + (size_t)kh * KHALF + col16 * 8;
    }
    const float* Sg = Sall + ((size_t)e * 16 + (n0 >> 7)) * KB + kh * (KB / 2);
    const float* Su = G1 ? (Sall + ((size_t)e * 16 + 8 + (n0 >> 7)) * KB + kh * (KB / 2)) : Sg;

    // ldmatrix per-lane address bases
    const int l2 = lane & 15;
    const uint32_t aFragBase = (uint32_t)((warpM + (lane & 7) + ((lane >> 3) & 1) * 8) * 144
                                          + ((lane >> 4) & 1) * 16);
    const uint32_t bFragBase = (uint32_t)((warpN + (l2 & 7)) * 144 + ((l2 >> 3) & 1) * 16);

    float acc[2][4][4];
#pragma unroll
    for (int mt = 0; mt < 2; mt++)
#pragma unroll
        for (int nt = 0; nt < 4; nt++)
#pragma unroll
            for (int i = 0; i < 4; i++) acc[mt][nt][i] = 0.f;

    // -------- prologue: fill stage 0; prefetch stages 1,2 --------
    {
#pragma unroll
        for (int i = 0; i < 2; i++)
            cpa16(sbase + ldoff + (uint32_t)(i * 4608),
                  Ah + (size_t)(rowg + 32 * i) * KTOT + col16 * 8);
        CP_COMMIT();
        if (pfth) {
#pragma unroll
            for (int pfs = 1; pfs <= 2 && pfs < KS; pfs++) {
#pragma unroll
                for (int i = 0; i < 4; i++) pf_l2(Bp[i] + pfs * 64);
#pragma unroll
                for (int i = 0; i < 2; i++)
                    if (col16 == 0)
                        pf_l2(Ah + (size_t)(rowg + 32 * i) * KTOT + pfs * 64);
            }
        }
#pragma unroll
        for (int i = 0; i < 4; i++) {
            float sc = (G1 && i >= 2) ? Su[0] : Sg[0];
            float4 u = *(const float4*)(Bp[i]);
            float4 v = *(const float4*)(Bp[i] + 4);
            sts128(sbase + 2 * A_STGB + ldoff + (uint32_t)(i * 4608),
                   pack_h2(u.x * sc, u.y * sc), pack_h2(u.z * sc, u.w * sc),
                   pack_h2(v.x * sc, v.y * sc), pack_h2(v.z * sc, v.w * sc));
        }
        CP_WAIT0();
        __syncthreads();
    }

    // -------- main loop --------
    for (int ks = 0; ks < KS; ks++) {
        const int cur = ks & 1, nxt = cur ^ 1;
        const uint32_t aCur = sbase + (uint32_t)(cur * A_STGB);
        const uint32_t bCur = sbase + (uint32_t)(2 * A_STGB + cur * B_STGB);

        float4 bu[4], bv[4];
        float  sc[4];
        const bool more = (ks + 1 < KS);
        if (more) {
            const int kf = (ks + 1) * 64;
            const int kb = (ks + 1) >> 1;
            const uint32_t aNxt = sbase + (uint32_t)(nxt * A_STGB);
#pragma unroll
            for (int i = 0; i < 2; i++)
                cpa16(aNxt + ldoff + (uint32_t)(i * 4608),
                      Ah + (size_t)(rowg + 32 * i) * KTOT + kf + col16 * 8);
            CP_COMMIT();
#pragma unroll
            for (int i = 0; i < 4; i++) {
                bu[i] = *(const float4*)(Bp[i] + kf);
                bv[i] = *(const float4*)(Bp[i] + kf + 4);
                sc[i] = (G1 && i >= 2) ? Su[kb] : Sg[kb];
            }
        }

        // prefetch stage ks+3 into L2 (lead ~2 stages before its LDG)
        if (ks + 3 < KS && pfth) {
            const int kp = (ks + 3) * 64;
#pragma unroll
            for (int i = 0; i < 4; i++) pf_l2(Bp[i] + kp);
            if (col16 == 0) {
#pragma unroll
                for (int i = 0; i < 2; i++)
                    pf_l2(Ah + (size_t)(rowg + 32 * i) * KTOT + kp);
            }
        }

        // compute on cur: 4 k16 steps
#pragma unroll
        for (int s = 0; s < 4; s++) {
            uint32_t af[2][4], bf[4][2];
#pragma unroll
            for (int mt = 0; mt < 2; mt++)
                ldsm4(af[mt][0], af[mt][1], af[mt][2], af[mt][3],
                      aCur + aFragBase + (uint32_t)(mt * 16 * 144 + s * 32));
#pragma unroll
            for (int nt = 0; nt < 4; nt++)
                ldsm2(bf[nt][0], bf[nt][1],
                      bCur + bFragBase + (uint32_t)(nt * 8 * 144 + s * 32));
#pragma unroll
            for (int mt = 0; mt < 2; mt++)
#pragma unroll
                for (int nt = 0; nt < 4; nt++)
                    mma16(acc[mt][nt], af[mt], bf[nt]);
        }

        if (more) {
            const uint32_t bNxt = sbase + (uint32_t)(2 * A_STGB + nxt * B_STGB);
#pragma unroll
            for (int i = 0; i < 4; i++) {
                sts128(bNxt + ldoff + (uint32_t)(i * 4608),
                       pack_h2(bu[i].x * sc[i], bu[i].y * sc[i]),
                       pack_h2(bu[i].z * sc[i], bu[i].w * sc[i]),
                       pack_h2(bv[i].x * sc[i], bv[i].y * sc[i]),
                       pack_h2(bv[i].z * sc[i], bv[i].w * sc[i]));
            }
            CP_WAIT0();
        }
        __syncthreads();
    }

    // -------- epilogue: raw partial stores (no silu; summed later) --------
    const int rr = lane >> 2, cc = (lane & 3) << 1;
    if (!G1) {
        float* Cb = (kh ? g_y2 : g_y1) + ((size_t)e * 512 + m0) * 2048 + n0;
#pragma unroll
        for (int mt = 0; mt < 2; mt++)
#pragma unroll
            for (int nt = 0; nt < 4; nt++) {
                float* p0 = Cb + (size_t)(warpM + mt * 16 + rr) * 2048 + warpN + nt * 8 + cc;
                *(float2*)p0 = make_float2(acc[mt][nt][0], acc[mt][nt][1]);
                *(float2*)(p0 + 8 * 2048) = make_float2(acc[mt][nt][2], acc[mt][nt][3]);
            }
    } else {
        float* Cb = (kh ? g_gu2 : g_gu1) + ((size_t)e * 512 + m0) * 2048;
        const int cb = warpN + cc;
        const int col = (cb < 64) ? (n0 + cb) : (1024 + n0 + cb - 64);
#pragma unroll
        for (int mt = 0; mt < 2; mt++)
#pragma unroll
            for (int nt = 0; nt < 4; nt++) {
                float* p0 = Cb + (size_t)(warpM + mt * 16 + rr) * 2048 + col + nt * 8;
                *(float2*)p0 = make_float2(acc[mt][nt][0], acc[mt][nt][1]);
                *(float2*)(p0 + 8 * 2048) = make_float2(acc[mt][nt][2], acc[mt][nt][3]);
            }
    }
}

// ---------------- activation: silu(g1+g2) * (u1+u2) -> fp16 -------------------
__global__ void act_kernel() {
    int idx = blockIdx.x * 256 + threadIdx.x;     // over 8*512*1024/4
    int row = idx >> 8;
    int e = row >> 9, m = row & 511;
    int lim = (g_cnt[e] + 63) & ~63;
    if (m >= lim) return;
    int i4 = (idx & 255) << 2;
    const float* b1 = g_gu1 + (size_t)row * 2048;
    const float* b2 = g_gu2 + (size_t)row * 2048;
    float4 ga = *(const float4*)(b1 + i4);
    float4 gb = *(const float4*)(b2 + i4);
    float4 ua = *(const float4*)(b1 + 1024 + i4);
    float4 ub = *(const float4*)(b2 + 1024 + i4);
    float g0 = ga.x + gb.x, g1 = ga.y + gb.y, g2 = ga.z + gb.z, g3 = ga.w + gb.w;
    float u0 = ua.x + ub.x, u1 = ua.y + ub.y, u2 = ua.z + ub.z, u3 = ua.w + ub.w;
    float a0 = g0 / (1.f + __expf(-g0)) * u0;
    float a1 = g1 / (1.f + __expf(-g1)) * u1;
    float a2 = g2 / (1.f + __expf(-g2)) * u2;
    float a3 = g3 / (1.f + __expf(-g3)) * u3;
    uint2 o;
    o.x = pack_h2(a0, a1);
    o.y = pack_h2(a2, a3);
    *(uint2*)(g_actE + (size_t)row * 1024 + i4) = o;
}

// ---------------- combine: out = w0*(y1+y2)[p0] + w1*(y1+y2)[p1] ---------------
__global__ void combine_kernel(const float* __restrict__ tw,
                               float* __restrict__ out) {
    int idx = blockIdx.x * 256 + threadIdx.x;     // over 256*2048/4
    int t  = idx >> 9;
    int h4 = (idx & 511) << 2;
    float w0 = tw[2 * t + 0], w1 = tw[2 * t + 1];
    size_t r0 = (size_t)g_pos[2 * t + 0] * 2048 + h4;
    size_t r1 = (size_t)g_pos[2 * t + 1] * 2048 + h4;
    float4 a1 = *(const float4*)(g_y1 + r0);
    float4 a2 = *(const float4*)(g_y2 + r0);
    float4 b1 = *(const float4*)(g_y1 + r1);
    float4 b2 = *(const float4*)(g_y2 + r1);
    *(float4*)(out + (size_t)t * 2048 + h4) = make_float4(
        w0 * (a1.x + a2.x) + w1 * (b1.x + b2.x),
        w0 * (a1.y + a2.y) + w1 * (b1.y + b2.y),
        w0 * (a1.z + a2.z) + w1 * (b1.z + b2.z),
        w0 * (a1.w + a2.w) + w1 * (b1.w + b2.w));
}

// ---------------- entry ---------------------------------------------------------
extern "C" void kernel_launch(void* const* d_in, const int* in_sizes, int n_in,
                              void* d_out, int out_size) {
    const float* x   = (const float*)d_in[0];
    const int*   ids = (const int*)d_in[1];
    const float* tw  = (const float*)d_in[2];
    const float* w13 = (const float*)d_in[3];
    const float* s13 = (const float*)d_in[4];
    const float* w2  = (const float*)d_in[5];
    const float* s2  = (const float*)d_in[6];
    float* out = (float*)d_out;

    cudaFuncSetAttribute(mma_gemm<2048, true>,  cudaFuncAttributeMaxDynamicSharedMemorySize, SMEM_DYN);
    cudaFuncSetAttribute(mma_gemm<1024, false>, cudaFuncAttributeMaxDynamicSharedMemorySize, SMEM_DYN);

    route_kernel<<<1, NPAIRS>>>(ids);
    gather_kernel<<<NEXP * 512, 256>>>(x);

    dim3 grid(16, 8, 16);               // n-tiles x m-tiles x (expert + khalf*8)
    mma_gemm<2048, true><<<grid, 256, SMEM_DYN>>>(w13, s13);   // gate_up partials
    act_kernel<<<(NEXP * 512 * 1024 / 4) / 256, 256>>>();      // sum + silu -> fp16
    mma_gemm<1024, false><<<grid, 256, SMEM_DYN>>>(w2, s2);    // down-proj partials
    combine_kernel<<<(NTOK * 2048 / 4) / 256, 256>>>(tw, out); // sum + weighted mix
}

// round 12
// speedup vs baseline: 1.6229x; 1.0180x over previous
#include <cuda_runtime.h>
#include <cuda_fp16.h>
#include <cstdint>

#define NTOK   256
#define NPAIRS 512
#define NEXP   8

// ---------------- scratch (device globals) ----------------------------------
__device__ int    g_cnt[NEXP];
__device__ int    g_pairs[NEXP][NPAIRS];
__device__ int    g_pos[NPAIRS];
__device__ __align__(16) __half g_Ah  [NEXP * 512 * 2048];   // gathered x rows, fp16
__device__ __align__(16) __half g_actE[NEXP * 512 * 1024];   // silu(gate)*up, fp16
__device__ float  g_yE  [NEXP * 512 * 2048];                 // GEMM2 out

// ---------------- helpers ----------------------------------------------------
__device__ __forceinline__ uint32_t smem_u32(const void* p) {
    uint32_t a;
    asm("{ .reg .u64 t; cvta.to.shared.u64 t, %1; cvt.u32.u64 %0, t; }" : "=r"(a) : "l"(p));
    return a;
}
__device__ __forceinline__ uint32_t pack_h2(float lo, float hi) {
    uint32_t r;
    asm("cvt.rn.f16x2.f32 %0, %1, %2;" : "=r"(r) : "f"(hi), "f"(lo));
    return r;
}
__device__ __forceinline__ void cpa16(uint32_t dst, const void* src) {
    asm volatile("cp.async.cg.shared.global [%0], [%1], 16;" :: "r"(dst), "l"(src));
}
#define CP_COMMIT() asm volatile("cp.async.commit_group;" ::: "memory")
#define CP_WAIT0()  asm volatile("cp.async.wait_group 0;" ::: "memory")
#define CP_WAIT1()  asm volatile("cp.async.wait_group 1;" ::: "memory")

__device__ __forceinline__ void bar_sync_id(int id) {
    asm volatile("bar.sync %0, 384;" :: "r"(id) : "memory");
}
__device__ __forceinline__ void bar_arrive_id(int id) {
    asm volatile("bar.arrive %0, 384;" :: "r"(id) : "memory");
}

__device__ __forceinline__ void sts128(uint32_t a, uint32_t x, uint32_t y, uint32_t z, uint32_t w) {
    asm volatile("st.shared.v4.b32 [%0], {%1, %2, %3, %4};" :: "r"(a), "r"(x), "r"(y), "r"(z), "r"(w) : "memory");
}
__device__ __forceinline__ void ldsm4(uint32_t& r0, uint32_t& r1, uint32_t& r2, uint32_t& r3, uint32_t a) {
    asm volatile("ldmatrix.sync.aligned.m8n8.x4.shared.b16 {%0,%1,%2,%3}, [%4];"
                 : "=r"(r0), "=r"(r1), "=r"(r2), "=r"(r3) : "r"(a));
}
__device__ __forceinline__ void ldsm2(uint32_t& r0, uint32_t& r1, uint32_t a) {
    asm volatile("ldmatrix.sync.aligned.m8n8.x2.shared.b16 {%0,%1}, [%2];"
                 : "=r"(r0), "=r"(r1) : "r"(a));
}
__device__ __forceinline__ void mma16(float* c, const uint32_t* a, const uint32_t* b) {
    asm volatile("mma.sync.aligned.m16n8k16.row.col.f32.f16.f16.f32 "
                 "{%0,%1,%2,%3}, {%4,%5,%6,%7}, {%8,%9}, {%0,%1,%2,%3};"
                 : "+f"(c[0]), "+f"(c[1]), "+f"(c[2]), "+f"(c[3])
                 : "r"(a[0]), "r"(a[1]), "r"(a[2]), "r"(a[3]), "r"(b[0]), "r"(b[1]));
}

// ---------------- routing ----------------------------------------------------
__global__ void route_kernel(const int* __restrict__ ids) {
    int tid = threadIdx.x;
    if (tid < NEXP) g_cnt[tid] = 0;
    __syncthreads();
    int e   = ids[tid] & 7;
    int pos = atomicAdd(&g_cnt[e], 1);
    g_pairs[e][pos] = tid;
    g_pos[tid] = e * 512 + pos;
}

// ---------------- gather x rows into padded fp16 A (128 rows/expert) ---------
__global__ void gather_kernel(const float* __restrict__ x) {
    int bid = blockIdx.x;               // NEXP*128 blocks: (e, m)
    int e = bid >> 7, m = bid & 127;
    int cnt = g_cnt[e];
    uint4* dst = (uint4*)(g_Ah + ((size_t)e * 512 + m) * 2048);
    int tid = threadIdx.x;
    if (m < cnt) {
        int p = g_pairs[e][m];
        const float4* src = (const float4*)(x + (size_t)(p >> 1) * 2048) + tid * 2;
        float4 v0 = src[0], v1 = src[1];
        uint4 o;
        o.x = pack_h2(v0.x, v0.y); o.y = pack_h2(v0.z, v0.w);
        o.z = pack_h2(v1.x, v1.y); o.w = pack_h2(v1.z, v1.w);
        dst[tid] = o;
    } else {
        dst[tid] = make_uint4(0, 0, 0, 0);
    }
}

// ---------------- warp-specialized fp16 mma GEMM -------------------------------
// 384 threads: warps 0-7 consumers (2m x 4n, warp tile 64x32), warps 8-11
// producers (B: LDG fp32 -> scale -> cvt fp16 -> STS). BM=128, BN=128, BK=64.
// SMEM ring: 3 x { B fp16 128x144B, A fp16 128x144B } = 110592 B, 1 CTA/SM.
// Handshake: FULL_b = bar id 1+b (producers arrive, consumers sync),
//            EMPTY_b = bar id 4+b (consumers arrive, producers sync). count=384.
// A: consumers cp.async 2 stages ahead (ring shares the 3 A buffers).
// G1 (n0=bx*64): B rows 0-63 gate (w13 n0+r), 64-127 up (w13 1024+n0+r-64);
//   epilogue silu(gate)*up -> g_actE fp16. G2 (n0=bx*128): w2 tile -> g_yE.
#define STGB 18432u                     // 128 rows * 144B
#define SMEM_DYN (6 * 18432)            // 110592

template<int KTOT, bool G1>
__global__ void __launch_bounds__(384, 1) mma_gemm(
    const float* __restrict__ Ball,
    const float* __restrict__ Sall)
{
    constexpr int KS = KTOT / 64;
    constexpr int KB = KTOT / 128;

    const int e   = blockIdx.z;
    const int cnt = g_cnt[e];
    if (cnt == 0) return;               // uniform per CTA
    const int n0  = G1 ? ((int)blockIdx.x << 6) : ((int)blockIdx.x << 7);

    const __half* Ah = (G1 ? g_Ah : g_actE) + (size_t)e * 512 * KTOT;

    extern __shared__ float dsm[];
    const uint32_t sb  = smem_u32(dsm);
    const uint32_t aA0 = sb + 3 * STGB;

    const int tid  = threadIdx.x;
    const int lane = tid & 31, w = tid >> 5;
    const int warpM = (w & 1) << 6;     // 0 or 64
    const int warpN = (w >> 1) << 5;    // 0,32,64,96 (consumer warps only)

    float acc[4][4][4] = {};            // consumer accumulators

    if (w >= 8) {
        // ================= producer: weight stream =================
        const int tp = tid - 256;       // 0..127
        const int rg = tp >> 3, c16 = tp & 7;
        const float* Bp[8];
        const float* Sp[8];
#pragma unroll
        for (int i = 0; i < 8; i++) {
            int row = rg + 16 * i;      // covers 0..127
            int n = G1 ? ((row < 64) ? (n0 + row) : (1024 + n0 + row - 64))
                       : (n0 + row);
            Bp[i] = Ball + ((size_t)e * 2048 + n) * KTOT + c16 * 8;
            Sp[i] = Sall + ((size_t)e * 16 + (G1 ? ((row < 64) ? 0 : 8) : 0)
                            + (n0 >> 7)) * KB;
        }
        for (int s = 0; s < KS; s++) {
            const int b  = s % 3;
            const int kf = s * 64;
            float4 u[8], v[8];
#pragma unroll
            for (int i = 0; i < 8; i++) {       // LDGs BEFORE the empty-wait
                u[i] = *(const float4*)(Bp[i] + kf);
                v[i] = *(const float4*)(Bp[i] + kf + 4);
            }
            bar_sync_id(4 + b);                 // buffer b free
            const uint32_t bB = sb + (uint32_t)b * STGB;
#pragma unroll
            for (int i = 0; i < 8; i++) {
                float sc = Sp[i][s >> 1];
                sts128(bB + (uint32_t)((rg + 16 * i) * 144 + c16 * 16),
                       pack_h2(u[i].x * sc, u[i].y * sc),
                       pack_h2(u[i].z * sc, u[i].w * sc),
                       pack_h2(v[i].x * sc, v[i].y * sc),
                       pack_h2(v[i].z * sc, v[i].w * sc));
            }
            bar_arrive_id(1 + b);               // buffer b full
        }
    } else {
        // ================= consumer: A cp.async + MMA =================
        const int l2 = lane & 15;
        const uint32_t aFB = (uint32_t)((warpM + (lane & 7) + ((lane >> 3) & 1) * 8) * 144
                                        + (lane >> 4) * 16);
        const uint32_t bFB = (uint32_t)((warpN + (l2 & 7)) * 144 + ((l2 >> 3) & 1) * 16);
        const int ar = tid >> 3, ac = tid & 7;  // A granules: rows ar+32j

        bar_arrive_id(4); bar_arrive_id(5); bar_arrive_id(6);   // bufs start empty

        // prologue: A stages 0,1 in flight
#pragma unroll
        for (int ps = 0; ps < 2; ps++) {
            const uint32_t dA = aA0 + (uint32_t)ps * STGB;
#pragma unroll
            for (int j = 0; j < 4; j++)
                cpa16(dA + (uint32_t)((ar + 32 * j) * 144 + ac * 16),
                      Ah + (size_t)(ar + 32 * j) * KTOT + ps * 64 + ac * 8);
            CP_COMMIT();
        }

        for (int s = 0; s < KS; s++) {
            const int b = s % 3;
            if (s + 1 < KS) CP_WAIT1(); else CP_WAIT0();  // A stage s landed
            bar_sync_id(1 + b);                           // B stage s ready (+A visible)
            if (s + 2 < KS) {                             // A stage s+2 into free buf
                const uint32_t dA = aA0 + (uint32_t)((s + 2) % 3) * STGB;
#pragma unroll
                for (int j = 0; j < 4; j++)
                    cpa16(dA + (uint32_t)((ar + 32 * j) * 144 + ac * 16),
                          Ah + (size_t)(ar + 32 * j) * KTOT + (s + 2) * 64 + ac * 8);
                CP_COMMIT();
            }
            const uint32_t bS = sb  + (uint32_t)b * STGB;
            const uint32_t aS = aA0 + (uint32_t)b * STGB;
#pragma unroll
            for (int ss = 0; ss < 4; ss++) {
                uint32_t af[4][4], bf[4][2];
#pragma unroll
                for (int mt = 0; mt < 4; mt++)
                    ldsm4(af[mt][0], af[mt][1], af[mt][2], af[mt][3],
                          aS + aFB + (uint32_t)(mt * 16 * 144 + ss * 32));
#pragma unroll
                for (int nt = 0; nt < 4; nt++)
                    ldsm2(bf[nt][0], bf[nt][1],
                          bS + bFB + (uint32_t)(nt * 8 * 144 + ss * 32));
#pragma unroll
                for (int mt = 0; mt < 4; mt++)
#pragma unroll
                    for (int nt = 0; nt < 4; nt++)
                        mma16(acc[mt][nt], af[mt], bf[nt]);
            }
            bar_arrive_id(4 + b);                         // buffer b free
        }
    }

    // ================= epilogue =================
    const int rr = lane >> 2, cc = (lane & 3) << 1;
    if (!G1) {
        if (w < 8) {
            float* Cb = g_yE + (size_t)e * 512 * 2048 + n0;
#pragma unroll
            for (int mt = 0; mt < 4; mt++)
#pragma unroll
                for (int nt = 0; nt < 4; nt++) {
                    float* p0 = Cb + (size_t)(warpM + mt * 16 + rr) * 2048 + warpN + nt * 8 + cc;
                    *(float2*)p0 = make_float2(acc[mt][nt][0], acc[mt][nt][1]);
                    *(float2*)(p0 + 8 * 2048) = make_float2(acc[mt][nt][2], acc[mt][nt][3]);
                }
        }
    } else {
        // fused silu(gate)*up: up warps (warpN>=64) stage accs via smem
        __syncthreads();
        float* ups = dsm;               // 128 rows x 68 floats (34.8KB, reuses ring)
        if (w < 8 && warpN >= 64) {
            const int wn = warpN - 64;
#pragma unroll
            for (int mt = 0; mt < 4; mt++)
#pragma unroll
                for (int nt = 0; nt < 4; nt++) {
                    int row = warpM + mt * 16 + rr;
                    int col = wn + nt * 8 + cc;
                    *(float2*)(ups + row * 68 + col)       = make_float2(acc[mt][nt][0], acc[mt][nt][1]);
                    *(float2*)(ups + (row + 8) * 68 + col) = make_float2(acc[mt][nt][2], acc[mt][nt][3]);
                }
        }
        __syncthreads();
        if (w < 8 && warpN < 64) {
            __half* act = g_actE + (size_t)e * 512 * 1024 + n0;
#pragma unroll
            for (int mt = 0; mt < 4; mt++)
#pragma unroll
                for (int nt = 0; nt < 4; nt++) {
                    int row = warpM + mt * 16 + rr;
                    int col = warpN + nt * 8 + cc;
                    float2 u0 = *(float2*)(ups + row * 68 + col);
                    float2 u1 = *(float2*)(ups + (row + 8) * 68 + col);
                    float g0 = acc[mt][nt][0], g1 = acc[mt][nt][1];
                    float g2 = acc[mt][nt][2], g3 = acc[mt][nt][3];
                    float a0 = g0 / (1.f + __expf(-g0)) * u0.x;
                    float a1 = g1 / (1.f + __expf(-g1)) * u0.y;
                    float a2 = g2 / (1.f + __expf(-g2)) * u1.x;
                    float a3 = g3 / (1.f + __expf(-g3)) * u1.y;
                    *(uint32_t*)(act + (size_t)row * 1024 + col)       = pack_h2(a0, a1);
                    *(uint32_t*)(act + (size_t)(row + 8) * 1024 + col) = pack_h2(a2, a3);
                }
        }
    }
}

// ---------------- combine -------------------------------------------------------
__global__ void combine_kernel(const float* __restrict__ tw,
                               float* __restrict__ out) {
    int idx = blockIdx.x * 256 + threadIdx.x;     // over 256*2048/4
    int t  = idx >> 9;
    int h4 = (idx & 511) << 2;
    float w0 = tw[2 * t + 0], w1 = tw[2 * t + 1];
    const float4* y0 = (const float4*)(g_yE + (size_t)g_pos[2 * t + 0] * 2048 + h4);
    const float4* y1 = (const float4*)(g_yE + (size_t)g_pos[2 * t + 1] * 2048 + h4);
    float4 a = *y0, b = *y1;
    *(float4*)(out + (size_t)t * 2048 + h4) = make_float4(
        w0 * a.x + w1 * b.x, w0 * a.y + w1 * b.y,
        w0 * a.z + w1 * b.z, w0 * a.w + w1 * b.w);
}

// ---------------- entry ---------------------------------------------------------
extern "C" void kernel_launch(void* const* d_in, const int* in_sizes, int n_in,
                              void* d_out, int out_size) {
    const float* x   = (const float*)d_in[0];
    const int*   ids = (const int*)d_in[1];
    const float* tw  = (const float*)d_in[2];
    const float* w13 = (const float*)d_in[3];
    const float* s13 = (const float*)d_in[4];
    const float* w2  = (const float*)d_in[5];
    const float* s2  = (const float*)d_in[6];
    float* out = (float*)d_out;

    cudaFuncSetAttribute(mma_gemm<2048, true>,  cudaFuncAttributeMaxDynamicSharedMemorySize, SMEM_DYN);
    cudaFuncSetAttribute(mma_gemm<1024, false>, cudaFuncAttributeMaxDynamicSharedMemorySize, SMEM_DYN);

    route_kernel<<<1, NPAIRS>>>(ids);
    gather_kernel<<<NEXP * 128, 256>>>(x);

    dim3 grid(16, 1, NEXP);             // 128 CTAs = one wave on 148 SMs
    mma_gemm<2048, true><<<grid, 384, SMEM_DYN>>>(w13, s13);   // gate_up + silu fused
    mma_gemm<1024, false><<<grid, 384, SMEM_DYN>>>(w2, s2);    // down proj

    combine_kernel<<<(NTOK * 2048 / 4) / 256, 256>>>(tw, out);
}